// round 8
// baseline (speedup 1.0000x reference)
#include <cuda_runtime.h>
#include <cstdint>

// Problem constants (fixed shapes for this problem instance).
static constexpr int       kNumPos = 8192;
static constexpr long long kNTot   = 32776192LL;            // 8192 + 8192*4000
static constexpr long long kMagicM = 34359739LL;            // ceil(2^37/4000)
static constexpr long long kMagicB = -281474981888LL;       // -8192*M
static constexpr int       kShift  = 37;

// Count-kernel geometry: 6 CTAs/SM x 152 SMs, 256 threads, 32KB smem (pos only).
static constexpr int NBLK_C = 912;
static constexpr int THR_C  = 256;
static constexpr int SMEM_C = kNumPos * 4;      // 32 KB

static constexpr int NBLK_A = 2048;             // scatter grid

__device__ float    g_pos[kNumPos];
__device__ unsigned g_hist[kNumPos];
__device__ int      g_is64;

// ---------------------------------------------------------------------------
__global__ void detect_kernel(const unsigned long long* __restrict__ idx) {
    if (threadIdx.x == 0 && blockIdx.x == 0) {
        int is64 = 1;
        #pragma unroll
        for (int i = 0; i < 64; ++i)
            if (idx[i] >= (unsigned long long)kNTot) is64 = 0;
        g_is64 = is64;
    }
}

// Dummy kernel: keeps ncu's fixed -s 5 capture slot on count_kernel.
__global__ void align_kernel() {}

// ---------------------------------------------------------------------------
// Pass A: scan index, scatter pos values; also zero g_hist and out[0].
// ---------------------------------------------------------------------------
__global__ void __launch_bounds__(256) scatter_pos_kernel(
    const void* __restrict__ idx_raw, const float* __restrict__ pred,
    float* __restrict__ out) {
    if (blockIdx.x == 0 && threadIdx.x == 0) out[0] = 0.0f;
    if (blockIdx.x < kNumPos / 256)
        g_hist[blockIdx.x * 256 + threadIdx.x] = 0u;   // ready before count launches

    const long long base   = blockIdx.x * 256LL + threadIdx.x;
    const long long stride = (long long)NBLK_A * 256LL;
    constexpr int U = 8;
    const long long bigstride = stride * U;

    if (g_is64) {
        const ulonglong2* idx2 = (const ulonglong2*)idx_raw;
        const long long nvec = kNTot / 2;
        const long long nmax = nvec - 1;
        const int iters = (int)((nvec + bigstride - 1) / bigstride);
        #pragma unroll 1
        for (int it = 0; it < iters; ++it) {
            ulonglong2 iv[U];
            #pragma unroll
            for (int u = 0; u < U; ++u) {
                long long v = base + (long long)it * bigstride + (long long)u * stride;
                iv[u] = idx2[v > nmax ? nmax : v];
            }
            #pragma unroll
            for (int u = 0; u < U; ++u) {
                long long v = base + (long long)it * bigstride + (long long)u * stride;
                if (v < nvec) {
                    if (iv[u].x < (unsigned long long)kNumPos) g_pos[iv[u].x] = pred[2 * v];
                    if (iv[u].y < (unsigned long long)kNumPos) g_pos[iv[u].y] = pred[2 * v + 1];
                }
            }
        }
    } else {
        const uint4* idx4 = (const uint4*)idx_raw;
        const long long nvec = kNTot / 4;
        const long long nmax = nvec - 1;
        const int iters = (int)((nvec + bigstride - 1) / bigstride);
        #pragma unroll 1
        for (int it = 0; it < iters; ++it) {
            uint4 iv[U];
            #pragma unroll
            for (int u = 0; u < U; ++u) {
                long long v = base + (long long)it * bigstride + (long long)u * stride;
                iv[u] = idx4[v > nmax ? nmax : v];
            }
            #pragma unroll
            for (int u = 0; u < U; ++u) {
                long long v = base + (long long)it * bigstride + (long long)u * stride;
                if (v < nvec) {
                    const long long e = 4 * v;
                    if (iv[u].x < (unsigned)kNumPos) g_pos[iv[u].x] = pred[e];
                    if (iv[u].y < (unsigned)kNumPos) g_pos[iv[u].y] = pred[e + 1];
                    if (iv[u].z < (unsigned)kNumPos) g_pos[iv[u].z] = pred[e + 2];
                    if (iv[u].w < (unsigned)kNumPos) g_pos[iv[u].w] = pred[e + 3];
                }
            }
        }
    }
}

// ---------------------------------------------------------------------------
// Pass B: compare against smem pos, fire-and-forget REDG increments into a
// single global histogram. No smem hists, no match, no dependency chains.
// ---------------------------------------------------------------------------
__device__ __forceinline__ void hist_step(unsigned i, float val,
                                          const float* __restrict__ s_pos) {
    // s = (i - 8192) / 4000; pos (i<8192) and OOB (~0u) wrap to s >= 8192.
    const unsigned s  = (unsigned)(((long long)i * kMagicM + kMagicB) >> kShift);
    const unsigned sm = s & 8191u;
    const float    p  = s_pos[sm];                 // masked -> always-safe addr
    if ((s < 8192u) && (val > p))
        atomicAdd(&g_hist[sm], 1u);                // result unused -> RED.E.ADD
}

__global__ void __launch_bounds__(THR_C, 6) count_kernel(
    const void* __restrict__ idx_raw, const float* __restrict__ pred) {
    extern __shared__ unsigned char smem_raw[];
    float* s_pos = (float*)smem_raw;
    const int tid = threadIdx.x;

    for (int k = tid; k < kNumPos; k += THR_C) s_pos[k] = g_pos[k];
    __syncthreads();

    constexpr int U = 4;
    if (g_is64) {
        const ulonglong2* idx2 = (const ulonglong2*)idx_raw;
        const float2*     val2 = (const float2*)pred;
        const long long nvec      = kNTot / 2;
        const long long stride    = (long long)NBLK_C * THR_C;
        const long long bigstride = stride * U;
        const long long base      = blockIdx.x * (long long)THR_C + tid;
        const int iters = (int)((nvec + bigstride - 1) / bigstride);
        for (int it = 0; it < iters; ++it) {
            ulonglong2 iv[U];
            float2     vv[U];
            #pragma unroll
            for (int u = 0; u < U; ++u) {
                const long long v = base + (long long)it * bigstride + (long long)u * stride;
                iv[u] = make_ulonglong2(~0ull, ~0ull);   // OOB -> skip
                vv[u] = make_float2(0.f, 0.f);
                if (v < nvec) { iv[u] = idx2[v]; vv[u] = val2[v]; }
            }
            #pragma unroll
            for (int u = 0; u < U; ++u) {
                hist_step((unsigned)iv[u].x, vv[u].x, s_pos);
                hist_step((unsigned)iv[u].y, vv[u].y, s_pos);
            }
        }
    } else {
        const uint4*  idx4 = (const uint4*)idx_raw;
        const float4* val4 = (const float4*)pred;
        const long long nvec      = kNTot / 4;
        const long long stride    = (long long)NBLK_C * THR_C;
        const long long bigstride = stride * U;
        const long long base      = blockIdx.x * (long long)THR_C + tid;
        const int iters = (int)((nvec + bigstride - 1) / bigstride);
        for (int it = 0; it < iters; ++it) {
            uint4  iv[U];
            float4 vv[U];
            #pragma unroll
            for (int u = 0; u < U; ++u) {
                const long long v = base + (long long)it * bigstride + (long long)u * stride;
                iv[u] = make_uint4(~0u, ~0u, ~0u, ~0u);  // OOB -> skip
                vv[u] = make_float4(0.f, 0.f, 0.f, 0.f);
                if (v < nvec) { iv[u] = idx4[v]; vv[u] = val4[v]; }
            }
            #pragma unroll
            for (int u = 0; u < U; ++u) {
                hist_step(iv[u].x, vv[u].x, s_pos);
                hist_step(iv[u].y, vv[u].y, s_pos);
                hist_step(iv[u].z, vv[u].z, s_pos);
                hist_step(iv[u].w, vv[u].w, s_pos);
            }
        }
    }
}

// ---------------------------------------------------------------------------
// Pass C: 32 blocks x 256 threads. out layout: [mrr, sample_mrr[8192]]
// ---------------------------------------------------------------------------
__global__ void __launch_bounds__(256) finalize_kernel(float* __restrict__ out) {
    const int bin = blockIdx.x * 256 + threadIdx.x;
    const unsigned c = g_hist[bin];
    const float mrr_i = 1.0f / (float)(1u + c);
    out[1 + bin] = mrr_i;

    float s = mrr_i;
    #pragma unroll
    for (int o = 16; o; o >>= 1) s += __shfl_down_sync(0xffffffffu, s, o);
    __shared__ float ws[8];
    const int lane = threadIdx.x & 31, warp = threadIdx.x >> 5;
    if (lane == 0) ws[warp] = s;
    __syncthreads();
    if (warp == 0) {
        s = (lane < 8) ? ws[lane] : 0.0f;
        #pragma unroll
        for (int o = 4; o; o >>= 1) s += __shfl_down_sync(0xffffffffu, s, o);
        if (lane == 0) atomicAdd(out, s * (1.0f / (float)kNumPos));
    }
}

// ---------------------------------------------------------------------------
extern "C" void kernel_launch(void* const* d_in, const int* in_sizes, int n_in,
                              void* d_out, int out_size) {
    const float* pred = (const float*)d_in[0];
    const void*  idx  = (const void*)d_in[1];
    float*       out  = (float*)d_out;

    detect_kernel<<<1, 32>>>((const unsigned long long*)idx);
    scatter_pos_kernel<<<NBLK_A, 256>>>(idx, pred, out);
    align_kernel<<<1, 32>>>();                 // keeps ncu slot 5 on count_kernel
    count_kernel<<<NBLK_C, THR_C, SMEM_C>>>(idx, pred);
    finalize_kernel<<<kNumPos / 256, 256>>>(out);
}

// round 12
// speedup vs baseline: 1.6567x; 1.6567x over previous
#include <cuda_runtime.h>
#include <cstdint>

// Problem constants (fixed shapes for this problem instance).
static constexpr int       kNumPos = 8192;
static constexpr long long kNTot   = 32776192LL;            // 8192 + 8192*4000
static constexpr long long kMagicM = 34359739LL;            // ceil(2^37/4000)
static constexpr long long kMagicB = -281474981888LL;       // -8192*M
static constexpr int       kShift  = 37;

// Count-kernel geometry: 6 CTAs/SM x 152 SMs, 256 threads, 32KB smem (pos only).
static constexpr int NBLK_C = 912;
static constexpr int THR_C  = 256;
static constexpr int SMEM_C = kNumPos * 4;      // 32 KB

static constexpr int NREP   = 8;                // histogram replicas (anti-serialization)
static constexpr int NBLK_A = 2048;             // scatter grid

__device__ float    g_pos[kNumPos];
__device__ unsigned g_hist[NREP * kNumPos];     // 256 KB
__device__ int      g_is64;

// ---------------------------------------------------------------------------
__global__ void detect_kernel(const unsigned long long* __restrict__ idx) {
    if (threadIdx.x == 0 && blockIdx.x == 0) {
        int is64 = 1;
        #pragma unroll
        for (int i = 0; i < 64; ++i)
            if (idx[i] >= (unsigned long long)kNTot) is64 = 0;
        g_is64 = is64;
    }
}

// Dummy kernel: keeps ncu's fixed -s 5 capture slot on count_kernel.
__global__ void align_kernel() {}

// ---------------------------------------------------------------------------
// Pass A: scan index, scatter pos values; also zero g_hist replicas and out[0].
// ---------------------------------------------------------------------------
__global__ void __launch_bounds__(256) scatter_pos_kernel(
    const void* __restrict__ idx_raw, const float* __restrict__ pred,
    float* __restrict__ out) {
    if (blockIdx.x == 0 && threadIdx.x == 0) out[0] = 0.0f;
    if (blockIdx.x < NREP * kNumPos / 256)
        g_hist[blockIdx.x * 256 + threadIdx.x] = 0u;   // ready before count launches

    const long long base   = blockIdx.x * 256LL + threadIdx.x;
    const long long stride = (long long)NBLK_A * 256LL;
    constexpr int U = 8;
    const long long bigstride = stride * U;

    if (g_is64) {
        const ulonglong2* idx2 = (const ulonglong2*)idx_raw;
        const long long nvec = kNTot / 2;
        const long long nmax = nvec - 1;
        const int iters = (int)((nvec + bigstride - 1) / bigstride);
        #pragma unroll 1
        for (int it = 0; it < iters; ++it) {
            ulonglong2 iv[U];
            #pragma unroll
            for (int u = 0; u < U; ++u) {
                long long v = base + (long long)it * bigstride + (long long)u * stride;
                iv[u] = idx2[v > nmax ? nmax : v];
            }
            #pragma unroll
            for (int u = 0; u < U; ++u) {
                long long v = base + (long long)it * bigstride + (long long)u * stride;
                if (v < nvec) {
                    if (iv[u].x < (unsigned long long)kNumPos) g_pos[iv[u].x] = pred[2 * v];
                    if (iv[u].y < (unsigned long long)kNumPos) g_pos[iv[u].y] = pred[2 * v + 1];
                }
            }
        }
    } else {
        const uint4* idx4 = (const uint4*)idx_raw;
        const long long nvec = kNTot / 4;
        const long long nmax = nvec - 1;
        const int iters = (int)((nvec + bigstride - 1) / bigstride);
        #pragma unroll 1
        for (int it = 0; it < iters; ++it) {
            uint4 iv[U];
            #pragma unroll
            for (int u = 0; u < U; ++u) {
                long long v = base + (long long)it * bigstride + (long long)u * stride;
                iv[u] = idx4[v > nmax ? nmax : v];
            }
            #pragma unroll
            for (int u = 0; u < U; ++u) {
                long long v = base + (long long)it * bigstride + (long long)u * stride;
                if (v < nvec) {
                    const long long e = 4 * v;
                    if (iv[u].x < (unsigned)kNumPos) g_pos[iv[u].x] = pred[e];
                    if (iv[u].y < (unsigned)kNumPos) g_pos[iv[u].y] = pred[e + 1];
                    if (iv[u].z < (unsigned)kNumPos) g_pos[iv[u].z] = pred[e + 2];
                    if (iv[u].w < (unsigned)kNumPos) g_pos[iv[u].w] = pred[e + 3];
                }
            }
        }
    }
}

// ---------------------------------------------------------------------------
// Pass B: compare against smem pos, fire-and-forget REDG increments into one
// of NREP global histogram replicas (selected per CTA) to break the LTS
// per-address atomic serialization.
// ---------------------------------------------------------------------------
__device__ __forceinline__ void hist_step(unsigned i, float val,
                                          const float* __restrict__ s_pos,
                                          unsigned* __restrict__ hist) {
    // s = (i - 8192) / 4000; pos (i<8192) and OOB (~0u) wrap to s >= 8192.
    const unsigned s  = (unsigned)(((long long)i * kMagicM + kMagicB) >> kShift);
    const unsigned sm = s & 8191u;
    const float    p  = s_pos[sm];                 // masked -> always-safe addr
    if ((s < 8192u) && (val > p))
        atomicAdd(&hist[sm], 1u);                  // result unused -> RED.E.ADD
}

__global__ void __launch_bounds__(THR_C, 6) count_kernel(
    const void* __restrict__ idx_raw, const float* __restrict__ pred) {
    extern __shared__ unsigned char smem_raw[];
    float* s_pos = (float*)smem_raw;
    const int tid = threadIdx.x;
    unsigned* hist = g_hist + (size_t)(blockIdx.x & (NREP - 1)) * kNumPos;

    for (int k = tid; k < kNumPos; k += THR_C) s_pos[k] = g_pos[k];
    __syncthreads();

    constexpr int U = 4;
    if (g_is64) {
        const ulonglong2* idx2 = (const ulonglong2*)idx_raw;
        const float2*     val2 = (const float2*)pred;
        const long long nvec      = kNTot / 2;
        const long long stride    = (long long)NBLK_C * THR_C;
        const long long bigstride = stride * U;
        const long long base      = blockIdx.x * (long long)THR_C + tid;
        const int iters = (int)((nvec + bigstride - 1) / bigstride);
        for (int it = 0; it < iters; ++it) {
            ulonglong2 iv[U];
            float2     vv[U];
            #pragma unroll
            for (int u = 0; u < U; ++u) {
                const long long v = base + (long long)it * bigstride + (long long)u * stride;
                iv[u] = make_ulonglong2(~0ull, ~0ull);   // OOB -> skip
                vv[u] = make_float2(0.f, 0.f);
                if (v < nvec) { iv[u] = idx2[v]; vv[u] = val2[v]; }
            }
            #pragma unroll
            for (int u = 0; u < U; ++u) {
                hist_step((unsigned)iv[u].x, vv[u].x, s_pos, hist);
                hist_step((unsigned)iv[u].y, vv[u].y, s_pos, hist);
            }
        }
    } else {
        const uint4*  idx4 = (const uint4*)idx_raw;
        const float4* val4 = (const float4*)pred;
        const long long nvec      = kNTot / 4;
        const long long stride    = (long long)NBLK_C * THR_C;
        const long long bigstride = stride * U;
        const long long base      = blockIdx.x * (long long)THR_C + tid;
        const int iters = (int)((nvec + bigstride - 1) / bigstride);
        for (int it = 0; it < iters; ++it) {
            uint4  iv[U];
            float4 vv[U];
            #pragma unroll
            for (int u = 0; u < U; ++u) {
                const long long v = base + (long long)it * bigstride + (long long)u * stride;
                iv[u] = make_uint4(~0u, ~0u, ~0u, ~0u);  // OOB -> skip
                vv[u] = make_float4(0.f, 0.f, 0.f, 0.f);
                if (v < nvec) { iv[u] = idx4[v]; vv[u] = val4[v]; }
            }
            #pragma unroll
            for (int u = 0; u < U; ++u) {
                hist_step(iv[u].x, vv[u].x, s_pos, hist);
                hist_step(iv[u].y, vv[u].y, s_pos, hist);
                hist_step(iv[u].z, vv[u].z, s_pos, hist);
                hist_step(iv[u].w, vv[u].w, s_pos, hist);
            }
        }
    }
}

// ---------------------------------------------------------------------------
// Pass C: 32 blocks x 256 threads. out layout: [mrr, sample_mrr[8192]]
// ---------------------------------------------------------------------------
__global__ void __launch_bounds__(256) finalize_kernel(float* __restrict__ out) {
    const int bin = blockIdx.x * 256 + threadIdx.x;
    unsigned c = 0;
    #pragma unroll
    for (int r = 0; r < NREP; ++r) c += g_hist[r * kNumPos + bin];
    const float mrr_i = 1.0f / (float)(1u + c);
    out[1 + bin] = mrr_i;

    float s = mrr_i;
    #pragma unroll
    for (int o = 16; o; o >>= 1) s += __shfl_down_sync(0xffffffffu, s, o);
    __shared__ float ws[8];
    const int lane = threadIdx.x & 31, warp = threadIdx.x >> 5;
    if (lane == 0) ws[warp] = s;
    __syncthreads();
    if (warp == 0) {
        s = (lane < 8) ? ws[lane] : 0.0f;
        #pragma unroll
        for (int o = 4; o; o >>= 1) s += __shfl_down_sync(0xffffffffu, s, o);
        if (lane == 0) atomicAdd(out, s * (1.0f / (float)kNumPos));
    }
}

// ---------------------------------------------------------------------------
extern "C" void kernel_launch(void* const* d_in, const int* in_sizes, int n_in,
                              void* d_out, int out_size) {
    const float* pred = (const float*)d_in[0];
    const void*  idx  = (const void*)d_in[1];
    float*       out  = (float*)d_out;

    detect_kernel<<<1, 32>>>((const unsigned long long*)idx);
    scatter_pos_kernel<<<NBLK_A, 256>>>(idx, pred, out);
    align_kernel<<<1, 32>>>();                 // keeps ncu slot 5 on count_kernel
    count_kernel<<<NBLK_C, THR_C, SMEM_C>>>(idx, pred);
    finalize_kernel<<<kNumPos / 256, 256>>>(out);
}

// round 14
// speedup vs baseline: 2.0039x; 1.2095x over previous
#include <cuda_runtime.h>
#include <cstdint>

// Problem constants (fixed shapes for this problem instance).
static constexpr int       kNumPos = 8192;
static constexpr long long kNTot   = 32776192LL;            // 8192 + 8192*4000
static constexpr long long kMagicM = 34359739LL;            // ceil(2^37/4000)
static constexpr long long kMagicB = -281474981888LL;       // -8192*M
static constexpr int       kShift  = 37;

// Count-kernel geometry: 6 CTAs/SM x 152 SMs, 256 threads, 32KB smem (pos only).
static constexpr int NBLK_C = 912;
static constexpr int THR_C  = 256;
static constexpr int SMEM_C = kNumPos * 4;      // 32 KB

static constexpr int NREP   = 64;               // histogram replicas (anti-serialization)
static constexpr int NBLK_A = 2048;             // scatter grid

__device__ float    g_pos[kNumPos];
__device__ unsigned g_hist[NREP * kNumPos];     // 2 MB, L2-resident
__device__ int      g_is64;

// ---------------------------------------------------------------------------
__global__ void detect_kernel(const unsigned long long* __restrict__ idx) {
    if (threadIdx.x == 0 && blockIdx.x == 0) {
        int is64 = 1;
        #pragma unroll
        for (int i = 0; i < 64; ++i)
            if (idx[i] >= (unsigned long long)kNTot) is64 = 0;
        g_is64 = is64;
    }
}

// Dummy kernel: keeps ncu's fixed -s 5 capture slot on count_kernel.
__global__ void align_kernel() {}

// ---------------------------------------------------------------------------
// Pass A: scan index, scatter pos values; also zero g_hist replicas and out[0].
// ---------------------------------------------------------------------------
__global__ void __launch_bounds__(256) scatter_pos_kernel(
    const void* __restrict__ idx_raw, const float* __restrict__ pred,
    float* __restrict__ out) {
    if (blockIdx.x == 0 && threadIdx.x == 0) out[0] = 0.0f;
    if (blockIdx.x < NREP * kNumPos / 256)
        g_hist[blockIdx.x * 256 + threadIdx.x] = 0u;   // 2048 blocks cover 2 MB

    const long long base   = blockIdx.x * 256LL + threadIdx.x;
    const long long stride = (long long)NBLK_A * 256LL;
    constexpr int U = 8;
    const long long bigstride = stride * U;

    if (g_is64) {
        const ulonglong2* idx2 = (const ulonglong2*)idx_raw;
        const long long nvec = kNTot / 2;
        const long long nmax = nvec - 1;
        const int iters = (int)((nvec + bigstride - 1) / bigstride);
        #pragma unroll 1
        for (int it = 0; it < iters; ++it) {
            ulonglong2 iv[U];
            #pragma unroll
            for (int u = 0; u < U; ++u) {
                long long v = base + (long long)it * bigstride + (long long)u * stride;
                iv[u] = idx2[v > nmax ? nmax : v];
            }
            #pragma unroll
            for (int u = 0; u < U; ++u) {
                long long v = base + (long long)it * bigstride + (long long)u * stride;
                if (v < nvec) {
                    if (iv[u].x < (unsigned long long)kNumPos) g_pos[iv[u].x] = pred[2 * v];
                    if (iv[u].y < (unsigned long long)kNumPos) g_pos[iv[u].y] = pred[2 * v + 1];
                }
            }
        }
    } else {
        const uint4* idx4 = (const uint4*)idx_raw;
        const long long nvec = kNTot / 4;
        const long long nmax = nvec - 1;
        const int iters = (int)((nvec + bigstride - 1) / bigstride);
        #pragma unroll 1
        for (int it = 0; it < iters; ++it) {
            uint4 iv[U];
            #pragma unroll
            for (int u = 0; u < U; ++u) {
                long long v = base + (long long)it * bigstride + (long long)u * stride;
                iv[u] = idx4[v > nmax ? nmax : v];
            }
            #pragma unroll
            for (int u = 0; u < U; ++u) {
                long long v = base + (long long)it * bigstride + (long long)u * stride;
                if (v < nvec) {
                    const long long e = 4 * v;
                    if (iv[u].x < (unsigned)kNumPos) g_pos[iv[u].x] = pred[e];
                    if (iv[u].y < (unsigned)kNumPos) g_pos[iv[u].y] = pred[e + 1];
                    if (iv[u].z < (unsigned)kNumPos) g_pos[iv[u].z] = pred[e + 2];
                    if (iv[u].w < (unsigned)kNumPos) g_pos[iv[u].w] = pred[e + 3];
                }
            }
        }
    }
}

// ---------------------------------------------------------------------------
// Pass B: compare against smem pos, fire-and-forget REDG increments into one
// of NREP global histogram replicas (selected per CTA) to break the LTS
// per-address atomic serialization.
// ---------------------------------------------------------------------------
__device__ __forceinline__ void hist_step(unsigned i, float val,
                                          const float* __restrict__ s_pos,
                                          unsigned* __restrict__ hist) {
    // s = (i - 8192) / 4000; pos (i<8192) and OOB (~0u) wrap to s >= 8192.
    const unsigned s  = (unsigned)(((long long)i * kMagicM + kMagicB) >> kShift);
    const unsigned sm = s & 8191u;
    const float    p  = s_pos[sm];                 // masked -> always-safe addr
    if ((s < 8192u) && (val > p))
        atomicAdd(&hist[sm], 1u);                  // result unused -> RED.E.ADD
}

__global__ void __launch_bounds__(THR_C, 6) count_kernel(
    const void* __restrict__ idx_raw, const float* __restrict__ pred) {
    extern __shared__ unsigned char smem_raw[];
    float* s_pos = (float*)smem_raw;
    const int tid = threadIdx.x;
    unsigned* hist = g_hist + (size_t)(blockIdx.x & (NREP - 1)) * kNumPos;

    for (int k = tid; k < kNumPos; k += THR_C) s_pos[k] = g_pos[k];
    __syncthreads();

    constexpr int U = 4;
    if (g_is64) {
        const ulonglong2* idx2 = (const ulonglong2*)idx_raw;
        const float2*     val2 = (const float2*)pred;
        const long long nvec      = kNTot / 2;
        const long long stride    = (long long)NBLK_C * THR_C;
        const long long bigstride = stride * U;
        const long long base      = blockIdx.x * (long long)THR_C + tid;
        const int iters = (int)((nvec + bigstride - 1) / bigstride);
        for (int it = 0; it < iters; ++it) {
            ulonglong2 iv[U];
            float2     vv[U];
            #pragma unroll
            for (int u = 0; u < U; ++u) {
                const long long v = base + (long long)it * bigstride + (long long)u * stride;
                iv[u] = make_ulonglong2(~0ull, ~0ull);   // OOB -> skip
                vv[u] = make_float2(0.f, 0.f);
                if (v < nvec) { iv[u] = idx2[v]; vv[u] = val2[v]; }
            }
            #pragma unroll
            for (int u = 0; u < U; ++u) {
                hist_step((unsigned)iv[u].x, vv[u].x, s_pos, hist);
                hist_step((unsigned)iv[u].y, vv[u].y, s_pos, hist);
            }
        }
    } else {
        const uint4*  idx4 = (const uint4*)idx_raw;
        const float4* val4 = (const float4*)pred;
        const long long nvec      = kNTot / 4;
        const long long stride    = (long long)NBLK_C * THR_C;
        const long long bigstride = stride * U;
        const long long base      = blockIdx.x * (long long)THR_C + tid;
        const int iters = (int)((nvec + bigstride - 1) / bigstride);
        for (int it = 0; it < iters; ++it) {
            uint4  iv[U];
            float4 vv[U];
            #pragma unroll
            for (int u = 0; u < U; ++u) {
                const long long v = base + (long long)it * bigstride + (long long)u * stride;
                iv[u] = make_uint4(~0u, ~0u, ~0u, ~0u);  // OOB -> skip
                vv[u] = make_float4(0.f, 0.f, 0.f, 0.f);
                if (v < nvec) { iv[u] = idx4[v]; vv[u] = val4[v]; }
            }
            #pragma unroll
            for (int u = 0; u < U; ++u) {
                hist_step(iv[u].x, vv[u].x, s_pos, hist);
                hist_step(iv[u].y, vv[u].y, s_pos, hist);
                hist_step(iv[u].z, vv[u].z, s_pos, hist);
                hist_step(iv[u].w, vv[u].w, s_pos, hist);
            }
        }
    }
}

// ---------------------------------------------------------------------------
// Pass C: 32 blocks x 256 threads. out layout: [mrr, sample_mrr[8192]]
// ---------------------------------------------------------------------------
__global__ void __launch_bounds__(256) finalize_kernel(float* __restrict__ out) {
    const int bin = blockIdx.x * 256 + threadIdx.x;
    unsigned c = 0;
    #pragma unroll 8
    for (int r = 0; r < NREP; ++r) c += g_hist[r * kNumPos + bin];
    const float mrr_i = 1.0f / (float)(1u + c);
    out[1 + bin] = mrr_i;

    float s = mrr_i;
    #pragma unroll
    for (int o = 16; o; o >>= 1) s += __shfl_down_sync(0xffffffffu, s, o);
    __shared__ float ws[8];
    const int lane = threadIdx.x & 31, warp = threadIdx.x >> 5;
    if (lane == 0) ws[warp] = s;
    __syncthreads();
    if (warp == 0) {
        s = (lane < 8) ? ws[lane] : 0.0f;
        #pragma unroll
        for (int o = 4; o; o >>= 1) s += __shfl_down_sync(0xffffffffu, s, o);
        if (lane == 0) atomicAdd(out, s * (1.0f / (float)kNumPos));
    }
}

// ---------------------------------------------------------------------------
extern "C" void kernel_launch(void* const* d_in, const int* in_sizes, int n_in,
                              void* d_out, int out_size) {
    const float* pred = (const float*)d_in[0];
    const void*  idx  = (const void*)d_in[1];
    float*       out  = (float*)d_out;

    detect_kernel<<<1, 32>>>((const unsigned long long*)idx);
    scatter_pos_kernel<<<NBLK_A, 256>>>(idx, pred, out);
    align_kernel<<<1, 32>>>();                 // keeps ncu slot 5 on count_kernel
    count_kernel<<<NBLK_C, THR_C, SMEM_C>>>(idx, pred);
    finalize_kernel<<<kNumPos / 256, 256>>>(out);
}

// round 15
// speedup vs baseline: 2.6728x; 1.3338x over previous
#include <cuda_runtime.h>
#include <cstdint>

// Problem constants (fixed shapes for this problem instance).
static constexpr int       kNumPos = 8192;
static constexpr int       kNumNeg = 4000;
static constexpr long long kNTot   = 32776192LL;            // 8192 + 8192*4000
static constexpr long long kMagicM = 34359739LL;            // ceil(2^37/4000)
static constexpr long long kMagicB = -281474981888LL;       // -8192*M
static constexpr int       kShift  = 37;

// Count-kernel geometry: 6 CTAs/SM x 152 SMs, 256 threads, 32KB smem (pos only).
static constexpr int NBLK_C = 912;
static constexpr int THR_C  = 256;
static constexpr int SMEM_C = kNumPos * 4;      // 32 KB

static constexpr int NREP   = 64;               // histogram replicas (anti-serialization)
static constexpr int NBLK_A = 2048;             // scatter grid

__device__ float    g_pos[kNumPos];
__device__ unsigned g_hist[NREP * kNumPos];     // 2 MB, L2-resident
__device__ int      g_is64;

// ---------------------------------------------------------------------------
__global__ void detect_kernel(const unsigned long long* __restrict__ idx) {
    if (threadIdx.x == 0 && blockIdx.x == 0) {
        int is64 = 1;
        #pragma unroll
        for (int i = 0; i < 64; ++i)
            if (idx[i] >= (unsigned long long)kNTot) is64 = 0;
        g_is64 = is64;
    }
}

// Dummy kernel: keeps ncu's fixed -s 5 capture slot on count_kernel.
__global__ void align_kernel() {}

// ---------------------------------------------------------------------------
// Pass A: scan index, scatter pos values; also zero g_hist replicas and out[0].
// ---------------------------------------------------------------------------
__global__ void __launch_bounds__(256) scatter_pos_kernel(
    const void* __restrict__ idx_raw, const float* __restrict__ pred,
    float* __restrict__ out) {
    if (blockIdx.x == 0 && threadIdx.x == 0) out[0] = 0.0f;
    if (blockIdx.x < NREP * kNumPos / 256)
        g_hist[blockIdx.x * 256 + threadIdx.x] = 0u;   // 2048 blocks cover 2 MB

    const long long base   = blockIdx.x * 256LL + threadIdx.x;
    const long long stride = (long long)NBLK_A * 256LL;
    constexpr int U = 8;
    const long long bigstride = stride * U;

    if (g_is64) {
        const ulonglong2* idx2 = (const ulonglong2*)idx_raw;
        const long long nvec = kNTot / 2;
        const long long nmax = nvec - 1;
        const int iters = (int)((nvec + bigstride - 1) / bigstride);
        #pragma unroll 1
        for (int it = 0; it < iters; ++it) {
            ulonglong2 iv[U];
            #pragma unroll
            for (int u = 0; u < U; ++u) {
                long long v = base + (long long)it * bigstride + (long long)u * stride;
                iv[u] = idx2[v > nmax ? nmax : v];
            }
            #pragma unroll
            for (int u = 0; u < U; ++u) {
                long long v = base + (long long)it * bigstride + (long long)u * stride;
                if (v < nvec) {
                    if (iv[u].x < (unsigned long long)kNumPos) g_pos[iv[u].x] = pred[2 * v];
                    if (iv[u].y < (unsigned long long)kNumPos) g_pos[iv[u].y] = pred[2 * v + 1];
                }
            }
        }
    } else {
        const uint4* idx4 = (const uint4*)idx_raw;
        const long long nvec = kNTot / 4;
        const long long nmax = nvec - 1;
        const int iters = (int)((nvec + bigstride - 1) / bigstride);
        #pragma unroll 1
        for (int it = 0; it < iters; ++it) {
            uint4 iv[U];
            #pragma unroll
            for (int u = 0; u < U; ++u) {
                long long v = base + (long long)it * bigstride + (long long)u * stride;
                iv[u] = idx4[v > nmax ? nmax : v];
            }
            #pragma unroll
            for (int u = 0; u < U; ++u) {
                long long v = base + (long long)it * bigstride + (long long)u * stride;
                if (v < nvec) {
                    const long long e = 4 * v;
                    if (iv[u].x < (unsigned)kNumPos) g_pos[iv[u].x] = pred[e];
                    if (iv[u].y < (unsigned)kNumPos) g_pos[iv[u].y] = pred[e + 1];
                    if (iv[u].z < (unsigned)kNumPos) g_pos[iv[u].z] = pred[e + 2];
                    if (iv[u].w < (unsigned)kNumPos) g_pos[iv[u].w] = pred[e + 3];
                }
            }
        }
    }
}

// ---------------------------------------------------------------------------
// Pass B: compare against smem pos; RED only on the statistically RARE side.
// If pos_s >= 0: count (val > p)   [P < 1/2]
// If pos_s <  0: count (val <= p)  [P < 1/2]; finalize computes 4000 - c.
// Expected REDs: ~1/4 of elements instead of ~1/2.
// ---------------------------------------------------------------------------
__device__ __forceinline__ void hist_step(unsigned i, float val,
                                          const float* __restrict__ s_pos,
                                          unsigned* __restrict__ hist) {
    // s = (i - 8192) / 4000; pos (i<8192) and OOB (~0u) wrap to s >= 8192.
    const unsigned s  = (unsigned)(((long long)i * kMagicM + kMagicB) >> kShift);
    const unsigned sm = s & 8191u;
    const float    p  = s_pos[sm];                 // masked -> always-safe addr
    const bool rare = (p < 0.0f) ? (val <= p) : (val > p);
    if ((s < 8192u) && rare)
        atomicAdd(&hist[sm], 1u);                  // result unused -> RED.E.ADD
}

__global__ void __launch_bounds__(THR_C, 6) count_kernel(
    const void* __restrict__ idx_raw, const float* __restrict__ pred) {
    extern __shared__ unsigned char smem_raw[];
    float* s_pos = (float*)smem_raw;
    const int tid = threadIdx.x;
    unsigned* hist = g_hist + (size_t)(blockIdx.x & (NREP - 1)) * kNumPos;

    for (int k = tid; k < kNumPos; k += THR_C) s_pos[k] = g_pos[k];
    __syncthreads();

    constexpr int U = 4;
    if (g_is64) {
        const ulonglong2* idx2 = (const ulonglong2*)idx_raw;
        const float2*     val2 = (const float2*)pred;
        const long long nvec      = kNTot / 2;
        const long long stride    = (long long)NBLK_C * THR_C;
        const long long bigstride = stride * U;
        const long long base      = blockIdx.x * (long long)THR_C + tid;
        const int iters = (int)((nvec + bigstride - 1) / bigstride);
        for (int it = 0; it < iters; ++it) {
            ulonglong2 iv[U];
            float2     vv[U];
            #pragma unroll
            for (int u = 0; u < U; ++u) {
                const long long v = base + (long long)it * bigstride + (long long)u * stride;
                iv[u] = make_ulonglong2(~0ull, ~0ull);   // OOB -> skip
                vv[u] = make_float2(0.f, 0.f);
                if (v < nvec) { iv[u] = idx2[v]; vv[u] = val2[v]; }
            }
            #pragma unroll
            for (int u = 0; u < U; ++u) {
                hist_step((unsigned)iv[u].x, vv[u].x, s_pos, hist);
                hist_step((unsigned)iv[u].y, vv[u].y, s_pos, hist);
            }
        }
    } else {
        const uint4*  idx4 = (const uint4*)idx_raw;
        const float4* val4 = (const float4*)pred;
        const long long nvec      = kNTot / 4;
        const long long stride    = (long long)NBLK_C * THR_C;
        const long long bigstride = stride * U;
        const long long base      = blockIdx.x * (long long)THR_C + tid;
        const int iters = (int)((nvec + bigstride - 1) / bigstride);
        for (int it = 0; it < iters; ++it) {
            uint4  iv[U];
            float4 vv[U];
            #pragma unroll
            for (int u = 0; u < U; ++u) {
                const long long v = base + (long long)it * bigstride + (long long)u * stride;
                iv[u] = make_uint4(~0u, ~0u, ~0u, ~0u);  // OOB -> skip
                vv[u] = make_float4(0.f, 0.f, 0.f, 0.f);
                if (v < nvec) { iv[u] = idx4[v]; vv[u] = val4[v]; }
            }
            #pragma unroll
            for (int u = 0; u < U; ++u) {
                hist_step(iv[u].x, vv[u].x, s_pos, hist);
                hist_step(iv[u].y, vv[u].y, s_pos, hist);
                hist_step(iv[u].z, vv[u].z, s_pos, hist);
                hist_step(iv[u].w, vv[u].w, s_pos, hist);
            }
        }
    }
}

// ---------------------------------------------------------------------------
// Pass C: 32 blocks x 256 threads. out layout: [mrr, sample_mrr[8192]]
// For bins counted on the complement side (pos < 0), c := 4000 - c.
// ---------------------------------------------------------------------------
__global__ void __launch_bounds__(256) finalize_kernel(float* __restrict__ out) {
    const int bin = blockIdx.x * 256 + threadIdx.x;
    unsigned c = 0;
    #pragma unroll 8
    for (int r = 0; r < NREP; ++r) c += g_hist[r * kNumPos + bin];
    if (g_pos[bin] < 0.0f) c = (unsigned)kNumNeg - c;
    const float mrr_i = 1.0f / (float)(1u + c);
    out[1 + bin] = mrr_i;

    float s = mrr_i;
    #pragma unroll
    for (int o = 16; o; o >>= 1) s += __shfl_down_sync(0xffffffffu, s, o);
    __shared__ float ws[8];
    const int lane = threadIdx.x & 31, warp = threadIdx.x >> 5;
    if (lane == 0) ws[warp] = s;
    __syncthreads();
    if (warp == 0) {
        s = (lane < 8) ? ws[lane] : 0.0f;
        #pragma unroll
        for (int o = 4; o; o >>= 1) s += __shfl_down_sync(0xffffffffu, s, o);
        if (lane == 0) atomicAdd(out, s * (1.0f / (float)kNumPos));
    }
}

// ---------------------------------------------------------------------------
extern "C" void kernel_launch(void* const* d_in, const int* in_sizes, int n_in,
                              void* d_out, int out_size) {
    const float* pred = (const float*)d_in[0];
    const void*  idx  = (const void*)d_in[1];
    float*       out  = (float*)d_out;

    detect_kernel<<<1, 32>>>((const unsigned long long*)idx);
    scatter_pos_kernel<<<NBLK_A, 256>>>(idx, pred, out);
    align_kernel<<<1, 32>>>();                 // keeps ncu slot 5 on count_kernel
    count_kernel<<<NBLK_C, THR_C, SMEM_C>>>(idx, pred);
    finalize_kernel<<<kNumPos / 256, 256>>>(out);
}